// round 2
// baseline (speedup 1.0000x reference)
#include <cuda_runtime.h>
#include <cstdint>

// ============================================================
// SKANLinear: y[b,o] = sum_i max(w[o,i] * x_aug[b,i], 0)
//   = 0.5 * ( X Wt + |X| |W|t )[b,o]  + relu(w[o,256])
// Single-accumulator dual tf32 mma.sync GEMM.
// ============================================================

#define B_ROWS 8192
#define OUT_N  256
#define K_MAIN 256

#define BDIM 512
#define BM 128
#define BN 128
#define KB 32
#define KCH (K_MAIN / KB)   // 8
#define LDA 36              // padded smem stride (floats)
#define ASZ (BM * LDA)      // 4608
#define BSZ (BN * LDA)      // 4608

// scratch: tf32-rounded, repacked weight (256x256) + relu(bias)
__device__ float g_Wp[OUT_N * K_MAIN];
__device__ float g_brelu[OUT_N];

__device__ __forceinline__ float to_tf32(float v) {
    uint32_t u;
    asm("cvt.rna.tf32.f32 %0, %1;" : "=r"(u) : "f"(v));
    return __uint_as_float(u);
}

__device__ __forceinline__ float abs_bits(float v) {
    return __uint_as_float(__float_as_uint(v) & 0x7fffffffu);
}

__device__ __forceinline__ void mma_tf32(float* c, const float* a, const float* b) {
    asm volatile(
        "mma.sync.aligned.m16n8k8.row.col.f32.tf32.tf32.f32 "
        "{%0,%1,%2,%3}, {%4,%5,%6,%7}, {%8,%9}, {%0,%1,%2,%3};"
        : "+f"(c[0]), "+f"(c[1]), "+f"(c[2]), "+f"(c[3])
        : "r"(__float_as_uint(a[0])), "r"(__float_as_uint(a[1])),
          "r"(__float_as_uint(a[2])), "r"(__float_as_uint(a[3])),
          "r"(__float_as_uint(b[0])), "r"(__float_as_uint(b[1])));
}

// --------- prep: repack weight (drop bias col), tf32-round, relu(bias) ----------
__global__ void skan_prep(const float* __restrict__ w) {
    int i = blockIdx.x * blockDim.x + threadIdx.x;   // 0..65535
    if (i < OUT_N * K_MAIN) {
        int o = i >> 8, k = i & 255;
        g_Wp[i] = to_tf32(w[o * 257 + k]);
    }
    if (i < OUT_N) {
        g_brelu[i] = fmaxf(w[i * 257 + 256], 0.0f);
    }
}

// --------- main GEMM ----------
__global__ void __launch_bounds__(BDIM, 1)
skan_gemm(const float* __restrict__ x, float* __restrict__ out) {
    extern __shared__ float sm[];
    float* As = sm;              // [2][BM][LDA]
    float* Bs = sm + 2 * ASZ;    // [2][BN][LDA]

    const int tid = threadIdx.x;
    const int wid = tid >> 5, ln = tid & 31;
    const int warpM = wid & 3, warpN = wid >> 2;     // 4x4 warp grid
    const int bm = blockIdx.x * BM;
    const int bn = blockIdx.y * BN;
    const int lg = ln >> 2;      // lane group 0..7
    const int lt = ln & 3;       // lane in group 0..3

    float acc[2][4][4];
    #pragma unroll
    for (int tm = 0; tm < 2; tm++)
        #pragma unroll
        for (int tn = 0; tn < 4; tn++)
            #pragma unroll
            for (int r = 0; r < 4; r++) acc[tm][tn][r] = 0.0f;

    float4 ra[2], rb[2];

    // producer index mapping: idx in [0,1024): row = idx>>3, kvec = (idx&7)*4
    #define LDG_CHUNK(c)                                                        \
        _Pragma("unroll")                                                       \
        for (int j = 0; j < 2; j++) {                                           \
            int idx = tid + j * BDIM;                                           \
            int row = idx >> 3, kv = (idx & 7) << 2;                            \
            ra[j] = *(const float4*)&x[(bm + row) * K_MAIN + (c) * KB + kv];    \
            rb[j] = *(const float4*)&g_Wp[(bn + row) * K_MAIN + (c) * KB + kv]; \
        }

    #define STS_CHUNK(buf)                                                      \
        _Pragma("unroll")                                                       \
        for (int j = 0; j < 2; j++) {                                           \
            int idx = tid + j * BDIM;                                           \
            int row = idx >> 3, kv = (idx & 7) << 2;                            \
            float4 a = ra[j];                                                   \
            a.x = to_tf32(a.x); a.y = to_tf32(a.y);                             \
            a.z = to_tf32(a.z); a.w = to_tf32(a.w);                             \
            *(float4*)&As[(buf) * ASZ + row * LDA + kv] = a;                    \
            *(float4*)&Bs[(buf) * BSZ + row * LDA + kv] = rb[j];                \
        }

    LDG_CHUNK(0);
    STS_CHUNK(0);
    __syncthreads();

    for (int c = 0; c < KCH; c++) {
        const int buf = c & 1;
        if (c + 1 < KCH) { LDG_CHUNK(c + 1); }

        const float* Ab = &As[buf * ASZ];
        const float* Bb = &Bs[buf * BSZ];

        #pragma unroll
        for (int ks = 0; ks < KB / 8; ks++) {
            const int k0 = ks * 8;

            float a[2][4], aa[2][4];
            #pragma unroll
            for (int tm = 0; tm < 2; tm++) {
                const int r0 = warpM * 32 + tm * 16 + lg;
                const float* p = &Ab[r0 * LDA + k0 + lt];
                a[tm][0] = p[0];
                a[tm][1] = p[8 * LDA];
                a[tm][2] = p[4];
                a[tm][3] = p[8 * LDA + 4];
                #pragma unroll
                for (int r = 0; r < 4; r++) aa[tm][r] = abs_bits(a[tm][r]);
            }

            float b[4][2], ab[4][2];
            #pragma unroll
            for (int tn = 0; tn < 4; tn++) {
                const int c0 = warpN * 32 + tn * 8 + lg;
                const float* p = &Bb[c0 * LDA + k0 + lt];
                b[tn][0] = p[0];
                b[tn][1] = p[4];
                ab[tn][0] = abs_bits(b[tn][0]);
                ab[tn][1] = abs_bits(b[tn][1]);
            }

            #pragma unroll
            for (int tm = 0; tm < 2; tm++)
                #pragma unroll
                for (int tn = 0; tn < 4; tn++) {
                    mma_tf32(acc[tm][tn], a[tm], b[tn]);     // X * Wt
                    mma_tf32(acc[tm][tn], aa[tm], ab[tn]);   // |X| * |W|t
                }
        }

        if (c + 1 < KCH) {
            __syncthreads();
            STS_CHUNK((c + 1) & 1);
            __syncthreads();
        }
    }

    // epilogue: y = 0.5*acc + relu(bias)
    #pragma unroll
    for (int tm = 0; tm < 2; tm++) {
        const int row = bm + warpM * 32 + tm * 16 + lg;
        #pragma unroll
        for (int tn = 0; tn < 4; tn++) {
            const int col = bn + warpN * 32 + tn * 8 + 2 * lt;
            const float br0 = g_brelu[col];
            const float br1 = g_brelu[col + 1];
            float2 v0, v1;
            v0.x = 0.5f * acc[tm][tn][0] + br0;
            v0.y = 0.5f * acc[tm][tn][1] + br1;
            v1.x = 0.5f * acc[tm][tn][2] + br0;
            v1.y = 0.5f * acc[tm][tn][3] + br1;
            *(float2*)&out[row * OUT_N + col]       = v0;
            *(float2*)&out[(row + 8) * OUT_N + col] = v1;
        }
    }
}

extern "C" void kernel_launch(void* const* d_in, const int* in_sizes, int n_in,
                              void* d_out, int out_size) {
    const float* x = (const float*)d_in[0];       // 8192 x 256
    const float* w = (const float*)d_in[1];       // 256 x 257
    float* out = (float*)d_out;                   // 8192 x 256

    skan_prep<<<(OUT_N * K_MAIN + 255) / 256, 256>>>(w);

    const int smem_bytes = (2 * ASZ + 2 * BSZ) * (int)sizeof(float);  // 73728
    cudaFuncSetAttribute(skan_gemm, cudaFuncAttributeMaxDynamicSharedMemorySize,
                         smem_bytes);
    dim3 grid(B_ROWS / BM, OUT_N / BN);   // 64 x 2 = 128 blocks, one wave
    skan_gemm<<<grid, BDIM, smem_bytes>>>(x, out);
}

// round 6
// speedup vs baseline: 1.2615x; 1.2615x over previous
#include <cuda_runtime.h>
#include <cuda_fp16.h>
#include <cstdint>

// ============================================================
// SKANLinear: y[b,o] = sum_i max(w[o,i] * x_aug[b,i], 0)
//   = 0.5 * ( X Wt + |X| |W|t ) + relu(w[o,256])
// Legacy-path f16 mma.m16n8k16 dual GEMM (fp32 accum).
//  - W block (128x256) converted to f16 once into resident smem
//  - A (x) double-buffered, K=64 per stage, 1 syncthreads/stage
//  - ldmatrix.x4 fragment loads, abs via LOP on f16x2 regs
// ============================================================

#define BM 128
#define BN 128
#define KD 256
#define WST 257
#define KB 64
#define NST 4
#define THREADS 512

// smem byte offsets
#define SM_BIAS 0                   // 128 f32
#define SM_A    1024                // 2 x 16384 (128 rows x 128B, swizzled)
#define SM_B    (1024 + 32768)      // 65536 (128 rows x 512B, swizzled)
#define SMEM_TOTAL (SM_B + 65536)   // 99328

__device__ __forceinline__ uint32_t smem_u32(const void* p) {
    uint32_t a;
    asm("{ .reg .u64 t; cvta.to.shared.u64 t, %1; cvt.u32.u64 %0, t; }" : "=r"(a) : "l"(p));
    return a;
}

__device__ __forceinline__ uint32_t f2h2(float lo, float hi) {
    __half2 h = __floats2half2_rn(lo, hi);
    return *(uint32_t*)&h;
}

__device__ __forceinline__ void ldsm4(uint32_t* r, uint32_t addr) {
    asm volatile("ldmatrix.sync.aligned.m8n8.x4.shared.b16 {%0,%1,%2,%3}, [%4];"
                 : "=r"(r[0]), "=r"(r[1]), "=r"(r[2]), "=r"(r[3]) : "r"(addr));
}

__device__ __forceinline__ void mma16816(float* c, const uint32_t* a,
                                         uint32_t b0, uint32_t b1) {
    asm volatile(
        "mma.sync.aligned.m16n8k16.row.col.f32.f16.f16.f32 "
        "{%0,%1,%2,%3}, {%4,%5,%6,%7}, {%8,%9}, {%0,%1,%2,%3};"
        : "+f"(c[0]), "+f"(c[1]), "+f"(c[2]), "+f"(c[3])
        : "r"(a[0]), "r"(a[1]), "r"(a[2]), "r"(a[3]), "r"(b0), "r"(b1));
}

__global__ void __launch_bounds__(THREADS, 1)
skan_f16(const float* __restrict__ x, const float* __restrict__ w,
         float* __restrict__ out) {
    extern __shared__ char sm[];
    const uint32_t smb = smem_u32(sm);
    const int tid = threadIdx.x;
    const int wid = tid >> 5, ln = tid & 31;
    const int warpM = wid & 3, warpN = wid >> 2;      // 4x4 warp grid
    const int bm = blockIdx.x * BM;
    const int bn = blockIdx.y * BN;

    // ---------------- prologue ----------------
    // A stage-0 LDG into regs (DRAM latency first)
    float4 ra[4];
    #pragma unroll
    for (int j = 0; j < 4; j++) {
        int idx = tid + j * THREADS;                  // 0..2047
        int row = idx >> 4, c4 = idx & 15;            // 128 rows x 16 float4
        ra[j] = *(const float4*)&x[(bm + row) * KD + c4 * 4];
    }

    // W block: 128 rows x 256 cols f32 -> f16 resident smem (512B rows, swizzled)
    #pragma unroll
    for (int j = 0; j < 8; j++) {
        int idx = tid + j * THREADS;                  // 0..4095
        int n = idx >> 5, c8 = idx & 31;              // 8 cols per slot
        const float* wp = &w[(bn + n) * WST + c8 * 8];
        float v0 = wp[0], v1 = wp[1], v2 = wp[2], v3 = wp[3];
        float v4 = wp[4], v5 = wp[5], v6 = wp[6], v7 = wp[7];
        uint4 pk;
        pk.x = f2h2(v0, v1); pk.y = f2h2(v2, v3);
        pk.z = f2h2(v4, v5); pk.w = f2h2(v6, v7);
        uint32_t off = (uint32_t)(c8 * 16) ^ (uint32_t)((n & 7) << 4);
        *(uint4*)(sm + SM_B + n * 512 + off) = pk;
    }

    // bias: relu(w[o,256])
    if (tid < 128) {
        *(float*)(sm + SM_BIAS + tid * 4) = fmaxf(w[(bn + tid) * WST + 256], 0.0f);
    }

    // A stage-0 STS (128B rows, SW128 swizzle)
    #pragma unroll
    for (int j = 0; j < 4; j++) {
        int idx = tid + j * THREADS;
        int row = idx >> 4, c4 = idx & 15;
        uint32_t off = (uint32_t)(c4 * 8) ^ (uint32_t)((row & 7) << 4);
        uint2 pk;
        pk.x = f2h2(ra[j].x, ra[j].y);
        pk.y = f2h2(ra[j].z, ra[j].w);
        *(uint2*)(sm + SM_A + row * 128 + off) = pk;
    }
    __syncthreads();

    // ---------------- per-lane ldmatrix address bases ----------------
    // A frag (m16k16): lanes 0-15 -> rows +0..15 @ k0 ; lanes 16-31 -> rows @ k0+8
    uint32_t baseA[2], m60A[2];
    {
        const int qA = (ln >> 4) * 16;                // byte offset of k-half
        #pragma unroll
        for (int tm = 0; tm < 2; tm++) {
            int rowl = warpM * 32 + tm * 16 + (ln & 15);
            uint32_t mA = (uint32_t)((rowl & 7) << 4);
            baseA[tm] = smb + SM_A + rowl * 128 + ((uint32_t)qA ^ (mA & 16u));
            m60A[tm] = mA & 0x60u;
        }
    }
    // B frag pair (two n8 tiles): lanes: n_off = (ln&7) + ((ln>>4)<<3), k-half = (ln>>3)&1
    uint32_t baseB[2], m60B[2];
    {
        const int noff = (ln & 7) + ((ln >> 4) << 3);
        const int khB = ((ln >> 3) & 1) * 16;
        #pragma unroll
        for (int p = 0; p < 2; p++) {
            int nl = warpN * 32 + p * 16 + noff;
            uint32_t mB = (uint32_t)((nl & 7) << 4);
            baseB[p] = smb + SM_B + nl * 512 + ((uint32_t)khB ^ (mB & 16u));
            m60B[p] = mB & 0x60u;
        }
    }

    float acc[2][4][4];
    #pragma unroll
    for (int tm = 0; tm < 2; tm++)
        #pragma unroll
        for (int tn = 0; tn < 4; tn++)
            #pragma unroll
            for (int r = 0; r < 4; r++) acc[tm][tn][r] = 0.0f;

    // ---------------- main loop: 4 stages, 1 sync per stage ----------------
    #pragma unroll
    for (int s = 0; s < NST; s++) {
        const uint32_t bufo = (uint32_t)((s & 1) * 16384);

        // prefetch next A stage into regs
        if (s + 1 < NST) {
            #pragma unroll
            for (int j = 0; j < 4; j++) {
                int idx = tid + j * THREADS;
                int row = idx >> 4, c4 = idx & 15;
                ra[j] = *(const float4*)&x[(bm + row) * KD + (s + 1) * KB + c4 * 4];
            }
        }

        // compute: 4 ksteps of k16
        #pragma unroll
        for (int ks = 0; ks < 4; ks++) {
            const uint32_t kb = (uint32_t)(ks * 32);
            uint32_t a[2][4], b[2][4], aa[2][4], bb[2][4];
            ldsm4(a[0], baseA[0] + bufo + (kb ^ m60A[0]));
            ldsm4(a[1], baseA[1] + bufo + (kb ^ m60A[1]));
            ldsm4(b[0], baseB[0] + (uint32_t)(s * 128) + (kb ^ m60B[0]));
            ldsm4(b[1], baseB[1] + (uint32_t)(s * 128) + (kb ^ m60B[1]));
            #pragma unroll
            for (int i = 0; i < 4; i++) {
                aa[0][i] = a[0][i] & 0x7FFF7FFFu;
                aa[1][i] = a[1][i] & 0x7FFF7FFFu;
                bb[0][i] = b[0][i] & 0x7FFF7FFFu;
                bb[1][i] = b[1][i] & 0x7FFF7FFFu;
            }
            #pragma unroll
            for (int tm = 0; tm < 2; tm++)
                #pragma unroll
                for (int tn = 0; tn < 4; tn++) {
                    const int p = tn >> 1, h = (tn & 1) * 2;
                    mma16816(acc[tm][tn], a[tm],  b[p][h],  b[p][h + 1]);   // X W^T
                    mma16816(acc[tm][tn], aa[tm], bb[p][h], bb[p][h + 1]);  // |X||W|^T
                }
        }

        // stage next A tile
        if (s + 1 < NST) {
            #pragma unroll
            for (int j = 0; j < 4; j++) {
                int idx = tid + j * THREADS;
                int row = idx >> 4, c4 = idx & 15;
                uint32_t off = (uint32_t)(c4 * 8) ^ (uint32_t)((row & 7) << 4);
                uint2 pk;
                pk.x = f2h2(ra[j].x, ra[j].y);
                pk.y = f2h2(ra[j].z, ra[j].w);
                *(uint2*)(sm + SM_A + ((s + 1) & 1) * 16384 + row * 128 + off) = pk;
            }
            __syncthreads();
        }
    }

    // ---------------- epilogue ----------------
    const int lg = ln >> 2, lt = ln & 3;
    #pragma unroll
    for (int tm = 0; tm < 2; tm++) {
        const int row = bm + warpM * 32 + tm * 16 + lg;
        #pragma unroll
        for (int tn = 0; tn < 4; tn++) {
            const int col = warpN * 32 + tn * 8 + 2 * lt;
            float2 bias = *(const float2*)(sm + SM_BIAS + col * 4);
            float2 v0, v1;
            v0.x = 0.5f * acc[tm][tn][0] + bias.x;
            v0.y = 0.5f * acc[tm][tn][1] + bias.y;
            v1.x = 0.5f * acc[tm][tn][2] + bias.x;
            v1.y = 0.5f * acc[tm][tn][3] + bias.y;
            *(float2*)&out[row * 256 + bn + col]       = v0;
            *(float2*)&out[(row + 8) * 256 + bn + col] = v1;
        }
    }
}

extern "C" void kernel_launch(void* const* d_in, const int* in_sizes, int n_in,
                              void* d_out, int out_size) {
    const float* x = (const float*)d_in[0];   // 8192 x 256
    const float* w = (const float*)d_in[1];   // 256 x 257
    float* out = (float*)d_out;               // 8192 x 256

    cudaFuncSetAttribute(skan_f16, cudaFuncAttributeMaxDynamicSharedMemorySize,
                         SMEM_TOTAL);
    dim3 grid(8192 / BM, 256 / BN);           // 64 x 2 = 128 CTAs, one wave
    skan_f16<<<grid, THREADS, SMEM_TOTAL>>>(x, w, out);
}

// round 11
// speedup vs baseline: 1.3957x; 1.1064x over previous
#include <cuda_runtime.h>
#include <cuda_fp16.h>
#include <cstdint>

// ============================================================
// SKANLinear: y[b,o] = sum_i max(w[o,i] * x_aug[b,i], 0)
//   = 0.5 * ( X Wt + |X| |W|t ) + relu(w[o,256])
// f16 mma.m16n8k16 dual GEMM (fp32 accum).
//  - W block loaded as coalesced flat float4 + divmod scatter
//    (bias column handled inline during scatter)
//  - A (x) double-buffered, K=64 per stage, 1 syncthreads/stage
//  - ldmatrix.x4 fragment loads, abs via LOP on f16x2 regs
// ============================================================

#define BM 128
#define BN 128
#define KD 256
#define WST 257
#define KB 64
#define NST 4
#define THREADS 512

// smem byte offsets
#define SM_BIAS 0                   // 128 f32
#define SM_A    1024                // 2 x 16384 (128 rows x 128B, swizzled)
#define SM_B    (1024 + 32768)      // 65536 (128 rows x 512B, swizzled)
#define SMEM_TOTAL (SM_B + 65536)   // 99328

__device__ __forceinline__ uint32_t smem_u32(const void* p) {
    uint32_t a;
    asm("{ .reg .u64 t; cvta.to.shared.u64 t, %1; cvt.u32.u64 %0, t; }" : "=r"(a) : "l"(p));
    return a;
}

__device__ __forceinline__ uint32_t f2h2(float lo, float hi) {
    __half2 h = __floats2half2_rn(lo, hi);
    return *(uint32_t*)&h;
}

__device__ __forceinline__ void ldsm4(uint32_t* r, uint32_t addr) {
    asm volatile("ldmatrix.sync.aligned.m8n8.x4.shared.b16 {%0,%1,%2,%3}, [%4];"
                 : "=r"(r[0]), "=r"(r[1]), "=r"(r[2]), "=r"(r[3]) : "r"(addr));
}

__device__ __forceinline__ void mma16816(float* c, const uint32_t* a,
                                         uint32_t b0, uint32_t b1) {
    asm volatile(
        "mma.sync.aligned.m16n8k16.row.col.f32.f16.f16.f32 "
        "{%0,%1,%2,%3}, {%4,%5,%6,%7}, {%8,%9}, {%0,%1,%2,%3};"
        : "+f"(c[0]), "+f"(c[1]), "+f"(c[2]), "+f"(c[3])
        : "r"(a[0]), "r"(a[1]), "r"(a[2]), "r"(a[3]), "r"(b0), "r"(b1));
}

__global__ void __launch_bounds__(THREADS, 1)
skan_f16(const float* __restrict__ x, const float* __restrict__ w,
         float* __restrict__ out) {
    extern __shared__ char sm[];
    const uint32_t smb = smem_u32(sm);
    const int tid = threadIdx.x;
    const int wid = tid >> 5, ln = tid & 31;
    const int warpM = wid & 3, warpN = wid >> 2;      // 4x4 warp grid
    const int bm = blockIdx.x * BM;
    const int bn = blockIdx.y * BN;

    // ---------------- prologue ----------------
    // A stage-0 LDG into regs (DRAM latency first)
    float4 ra[4];
    #pragma unroll
    for (int j = 0; j < 4; j++) {
        int idx = tid + j * THREADS;                  // 0..2047
        int row = idx >> 4, c4 = idx & 15;            // 128 rows x 16 float4
        ra[j] = *(const float4*)&x[(bm + row) * KD + c4 * 4];
    }

    // W block rows [bn, bn+128): a CONTIGUOUS flat range of 128*257 = 32896
    // floats. Load coalesced as float4 (8224 vecs), divmod-scatter into the
    // swizzled f16 smem tile; col 256 is the bias -> relu into SM_BIAS.
    {
        const float* wflat = w + (size_t)bn * WST;
        #pragma unroll
        for (int j = 0; j < 17; j++) {
            int f = tid + j * THREADS;                // float4 index
            if (f < 8224) {
                float4 v = *(const float4*)&wflat[f * 4];
                int e0 = f * 4;
                int n = e0 / 257;
                int c = e0 - n * 257;
                float vv[4] = {v.x, v.y, v.z, v.w};
                #pragma unroll
                for (int u = 0; u < 4; u++) {
                    if (c == 257) { c = 0; n++; }
                    if (c < 256) {
                        uint16_t h = __half_as_ushort(__float2half_rn(vv[u]));
                        uint32_t off = (uint32_t)(c * 2) ^ (uint32_t)((n & 7) << 4);
                        *(uint16_t*)(sm + SM_B + n * 512 + off) = h;
                    } else {
                        *(float*)(sm + SM_BIAS + n * 4) = fmaxf(vv[u], 0.0f);
                    }
                    c++;
                }
            }
        }
    }

    // A stage-0 STS (128B rows, SW128 swizzle)
    #pragma unroll
    for (int j = 0; j < 4; j++) {
        int idx = tid + j * THREADS;
        int row = idx >> 4, c4 = idx & 15;
        uint32_t off = (uint32_t)(c4 * 8) ^ (uint32_t)((row & 7) << 4);
        uint2 pk;
        pk.x = f2h2(ra[j].x, ra[j].y);
        pk.y = f2h2(ra[j].z, ra[j].w);
        *(uint2*)(sm + SM_A + row * 128 + off) = pk;
    }
    __syncthreads();

    // ---------------- per-lane ldmatrix address bases ----------------
    uint32_t baseA[2], m60A[2];
    {
        const int qA = (ln >> 4) * 16;                // byte offset of k-half
        #pragma unroll
        for (int tm = 0; tm < 2; tm++) {
            int rowl = warpM * 32 + tm * 16 + (ln & 15);
            uint32_t mA = (uint32_t)((rowl & 7) << 4);
            baseA[tm] = smb + SM_A + rowl * 128 + ((uint32_t)qA ^ (mA & 16u));
            m60A[tm] = mA & 0x60u;
        }
    }
    uint32_t baseB[2], m60B[2];
    {
        const int noff = (ln & 7) + ((ln >> 4) << 3);
        const int khB = ((ln >> 3) & 1) * 16;
        #pragma unroll
        for (int p = 0; p < 2; p++) {
            int nl = warpN * 32 + p * 16 + noff;
            uint32_t mB = (uint32_t)((nl & 7) << 4);
            baseB[p] = smb + SM_B + nl * 512 + ((uint32_t)khB ^ (mB & 16u));
            m60B[p] = mB & 0x60u;
        }
    }

    float acc[2][4][4];
    #pragma unroll
    for (int tm = 0; tm < 2; tm++)
        #pragma unroll
        for (int tn = 0; tn < 4; tn++)
            #pragma unroll
            for (int r = 0; r < 4; r++) acc[tm][tn][r] = 0.0f;

    // ---------------- main loop: 4 stages, 1 sync per stage ----------------
    #pragma unroll
    for (int s = 0; s < NST; s++) {
        const uint32_t bufo = (uint32_t)((s & 1) * 16384);

        // prefetch next A stage into regs
        if (s + 1 < NST) {
            #pragma unroll
            for (int j = 0; j < 4; j++) {
                int idx = tid + j * THREADS;
                int row = idx >> 4, c4 = idx & 15;
                ra[j] = *(const float4*)&x[(bm + row) * KD + (s + 1) * KB + c4 * 4];
            }
        }

        // compute: 4 ksteps of k16
        #pragma unroll
        for (int ks = 0; ks < 4; ks++) {
            const uint32_t kb = (uint32_t)(ks * 32);
            uint32_t a[2][4], b[2][4], aa[2][4], bb[2][4];
            ldsm4(a[0], baseA[0] + bufo + (kb ^ m60A[0]));
            ldsm4(a[1], baseA[1] + bufo + (kb ^ m60A[1]));
            ldsm4(b[0], baseB[0] + (uint32_t)(s * 128) + (kb ^ m60B[0]));
            ldsm4(b[1], baseB[1] + (uint32_t)(s * 128) + (kb ^ m60B[1]));
            #pragma unroll
            for (int i = 0; i < 4; i++) {
                aa[0][i] = a[0][i] & 0x7FFF7FFFu;
                aa[1][i] = a[1][i] & 0x7FFF7FFFu;
                bb[0][i] = b[0][i] & 0x7FFF7FFFu;
                bb[1][i] = b[1][i] & 0x7FFF7FFFu;
            }
            #pragma unroll
            for (int tm = 0; tm < 2; tm++)
                #pragma unroll
                for (int tn = 0; tn < 4; tn++) {
                    const int p = tn >> 1, h = (tn & 1) * 2;
                    mma16816(acc[tm][tn], a[tm],  b[p][h],  b[p][h + 1]);   // X W^T
                    mma16816(acc[tm][tn], aa[tm], bb[p][h], bb[p][h + 1]);  // |X||W|^T
                }
        }

        // stage next A tile
        if (s + 1 < NST) {
            #pragma unroll
            for (int j = 0; j < 4; j++) {
                int idx = tid + j * THREADS;
                int row = idx >> 4, c4 = idx & 15;
                uint32_t off = (uint32_t)(c4 * 8) ^ (uint32_t)((row & 7) << 4);
                uint2 pk;
                pk.x = f2h2(ra[j].x, ra[j].y);
                pk.y = f2h2(ra[j].z, ra[j].w);
                *(uint2*)(sm + SM_A + ((s + 1) & 1) * 16384 + row * 128 + off) = pk;
            }
            __syncthreads();
        }
    }

    // ---------------- epilogue ----------------
    const int lg = ln >> 2, lt = ln & 3;
    #pragma unroll
    for (int tm = 0; tm < 2; tm++) {
        const int row = bm + warpM * 32 + tm * 16 + lg;
        #pragma unroll
        for (int tn = 0; tn < 4; tn++) {
            const int col = warpN * 32 + tn * 8 + 2 * lt;
            float2 bias = *(const float2*)(sm + SM_BIAS + col * 4);
            float2 v0, v1;
            v0.x = 0.5f * acc[tm][tn][0] + bias.x;
            v0.y = 0.5f * acc[tm][tn][1] + bias.y;
            v1.x = 0.5f * acc[tm][tn][2] + bias.x;
            v1.y = 0.5f * acc[tm][tn][3] + bias.y;
            *(float2*)&out[row * 256 + bn + col]       = v0;
            *(float2*)&out[(row + 8) * 256 + bn + col] = v1;
        }
    }
}

extern "C" void kernel_launch(void* const* d_in, const int* in_sizes, int n_in,
                              void* d_out, int out_size) {
    const float* x = (const float*)d_in[0];   // 8192 x 256
    const float* w = (const float*)d_in[1];   // 256 x 257
    float* out = (float*)d_out;               // 8192 x 256

    cudaFuncSetAttribute(skan_f16, cudaFuncAttributeMaxDynamicSharedMemorySize,
                         SMEM_TOTAL);
    dim3 grid(8192 / BM, 256 / BN);           // 64 x 2 = 128 CTAs, one wave
    skan_f16<<<grid, THREADS, SMEM_TOTAL>>>(x, w, out);
}